// round 13
// baseline (speedup 1.0000x reference)
#include <cuda_runtime.h>
#include <cuda_fp16.h>
#include <math.h>
#include <stdint.h>

// Problem constants
#define BS     2048
#define LTOK   49
#define DMODEL 512
#define NHEAD  16
#define HDIM   32
#define NMASK  64
#define MROWS  (BS * LTOK)          // 100352
#define N_QKV  (3 * DMODEL)         // 1536
#define LL     (LTOK * LTOK)        // 2401

// Scratch (device globals: allocation-free per harness rules)
__device__ __half g_qkv_h[(size_t)MROWS * N_QKV];         // qkv as fp16
__device__ __half g_x_h[(size_t)MROWS * DMODEL];          // x as fp16
__device__ __half g_ctx_h[(size_t)MROWS * DMODEL];        // ctx as fp16
__device__ __half g_wqkvT_h[(size_t)N_QKV * DMODEL];      // W^T [N,K] fp16
__device__ __half g_woutT_h[(size_t)DMODEL * DMODEL];
__device__ float g_cbias[NMASK * LL];                     // combined relpos-bias + mask

// ---------------------------------------------------------------------------
// PTX helpers (sm_80-compatible: cp.async + ldmatrix + mma.sync only)
// ---------------------------------------------------------------------------
__device__ __forceinline__ uint32_t smem_u32(const void* p) {
    uint32_t a;
    asm("{ .reg .u64 t; cvta.to.shared.u64 t, %1; cvt.u32.u64 %0, t; }" : "=r"(a) : "l"(p));
    return a;
}
#define CP_ASYNC16(dst, src) \
    asm volatile("cp.async.cg.shared.global [%0], [%1], 16;" :: "r"(dst), "l"(src))
#define CP_COMMIT() asm volatile("cp.async.commit_group;" ::: "memory")
#define CP_WAIT(n)  asm volatile("cp.async.wait_group %0;" :: "n"(n) : "memory")

__device__ __forceinline__ void ldmx4(uint32_t* r, uint32_t addr) {
    asm volatile("ldmatrix.sync.aligned.m8n8.x4.shared.b16 {%0,%1,%2,%3}, [%4];"
                 : "=r"(r[0]), "=r"(r[1]), "=r"(r[2]), "=r"(r[3]) : "r"(addr));
}
__device__ __forceinline__ void mma16816(float* d, const uint32_t* a, const uint32_t* b) {
    asm volatile(
        "mma.sync.aligned.m16n8k16.row.col.f32.f16.f16.f32 "
        "{%0,%1,%2,%3}, {%4,%5,%6,%7}, {%8,%9}, {%0,%1,%2,%3};"
        : "+f"(d[0]), "+f"(d[1]), "+f"(d[2]), "+f"(d[3])
        : "r"(a[0]), "r"(a[1]), "r"(a[2]), "r"(a[3]), "r"(b[0]), "r"(b[1]));
}

// SW128: 128-byte smem rows; 16B-chunk index XOR row&7 -> conflict-free
__device__ __forceinline__ uint32_t sw128(int row, int chunk16) {
    return (uint32_t)(row * 128 + ((chunk16 ^ (row & 7)) << 4));
}

// ---------------------------------------------------------------------------
// Prep kernels
// ---------------------------------------------------------------------------
// One kernel for all fp16 conversions: x (vec4), wqkv^T, wout^T (scalar).
#define XW4   (MROWS * DMODEL / 4)            // 12,845,056 float4 units
#define WQKVN (N_QKV * DMODEL)                // 786,432
#define WOUTN (DMODEL * DMODEL)               // 262,144
#define PREP_TOTAL (XW4 + WQKVN + WOUTN)

__global__ void prep_pre(const float* __restrict__ x,
                         const float* __restrict__ w_qkv,
                         const float* __restrict__ w_out,
                         __half* __restrict__ xh,
                         __half* __restrict__ wqh,
                         __half* __restrict__ woh)
{
    int i = blockIdx.x * blockDim.x + threadIdx.x;
    if (i < XW4) {
        float4 v = ((const float4*)x)[i];
        ((__half2*)xh)[i * 2 + 0] = __floats2half2_rn(v.x, v.y);
        ((__half2*)xh)[i * 2 + 1] = __floats2half2_rn(v.z, v.w);
    } else if (i < XW4 + WQKVN) {
        int idx = i - XW4;                     // n*K + k
        int n = idx / DMODEL, k = idx - n * DMODEL;
        wqh[idx] = __float2half_rn(w_qkv[(size_t)k * N_QKV + n]);
    } else if (i < PREP_TOTAL) {
        int idx = i - XW4 - WQKVN;
        int n = idx / DMODEL, k = idx - n * DMODEL;
        woh[idx] = __float2half_rn(w_out[(size_t)k * DMODEL + n]);
    }
}

__global__ void prep_cbias(const float* __restrict__ bias_table,
                           const int* __restrict__ rel_index,
                           const float* __restrict__ mask)
{
    int i = blockIdx.x * blockDim.x + threadIdx.x;
    if (i >= NMASK * LL) return;
    int w = i / LL, idx = i - w * LL;
    int h = w & 15;
    g_cbias[i] = bias_table[rel_index[idx] * NHEAD + h] + mask[(size_t)w * LL + idx];
}

// ---------------------------------------------------------------------------
// mma.sync GEMM: C[M,N] = A[M,K](fp16) @ B[N,K](fp16)^T + bias (fp32 acc)
// 128x128 CTA tile, 4 warps (warp tile 64x64), BK=64, 128 threads,
// 3-stage cp.async pipeline (32KB/stage), fragment double-buffering, 2 CTA/SM.
// ---------------------------------------------------------------------------
#define GBM 128
#define GBN 128
#define GBK 64
#define TILEB (128 * 128)               // 16384 (128 rows x 128B)
#define STAGEB (2 * TILEB)              // 32768 (A + B)
#define NSTAGE 3
#define SM_A 0
#define SM_B TILEB
#define SM_TOTAL (NSTAGE * STAGEB)      // 98304

template <typename OutT>
__global__ __launch_bounds__(128, 2) void gemm_mma(
    const __half* __restrict__ A, const __half* __restrict__ B,
    const float* __restrict__ bias, OutT* __restrict__ C,
    int M, int N, int K)
{
    extern __shared__ char smem[];
    const uint32_t sbase = smem_u32(smem);
    const int tid = threadIdx.x;
    const int lane = tid & 31;
    const int wid = tid >> 5;
    const int warp_m = wid & 1;
    const int warp_n = wid >> 1;
    const int bm = blockIdx.y * GBM;
    const int bn = blockIdx.x * GBN;

    float acc[4][8][4];
    #pragma unroll
    for (int mi = 0; mi < 4; mi++)
        #pragma unroll
        for (int ni = 0; ni < 8; ni++)
            #pragma unroll
            for (int e = 0; e < 4; e++) acc[mi][ni][e] = 0.0f;

    const int nch = K / GBK;            // 8

    auto load_stage = [&](int ch, int s) {
        const int k0 = ch * GBK;
        const uint32_t stbase = sbase + (uint32_t)s * STAGEB;
        #pragma unroll
        for (int i = 0; i < 8; i++) {
            int u = tid + i * 128;
            int row = u >> 3, c16 = u & 7;
            const void* srcA = A + (size_t)(bm + row) * K + k0 + c16 * 8;
            CP_ASYNC16(stbase + SM_A + sw128(row, c16), srcA);
            const void* srcB = B + (size_t)(bn + row) * K + k0 + c16 * 8;
            CP_ASYNC16(stbase + SM_B + sw128(row, c16), srcB);
        }
        CP_COMMIT();
    };

    load_stage(0, 0);
    load_stage(1, 1);

    uint32_t a_f[2][4][4], b_f[2][4][4];
    const int ar = lane & 15;
    const int ac16 = (lane >> 4);
    const int br = (lane & 7) + ((lane >> 4) << 3);
    const int bc16 = ((lane >> 3) & 1);

    int slot = 0;
    for (int ch = 0; ch < nch; ch++) {
        if (ch + 1 < nch) { CP_WAIT(1); } else { CP_WAIT(0); }
        __syncthreads();
        if (ch + 2 < nch) load_stage(ch + 2, (slot + 2) % NSTAGE);

        const uint32_t st = sbase + (uint32_t)slot * STAGEB;

        #pragma unroll
        for (int mi = 0; mi < 4; mi++)
            ldmx4(a_f[0][mi], st + SM_A + sw128(warp_m * 64 + mi * 16 + ar, ac16));
        #pragma unroll
        for (int nb = 0; nb < 4; nb++)
            ldmx4(b_f[0][nb], st + SM_B + sw128(warp_n * 64 + nb * 16 + br, bc16));

        #pragma unroll
        for (int kk = 0; kk < 4; kk++) {
            const int cur = kk & 1, nxt = cur ^ 1;
            if (kk < 3) {
                #pragma unroll
                for (int mi = 0; mi < 4; mi++)
                    ldmx4(a_f[nxt][mi],
                          st + SM_A + sw128(warp_m * 64 + mi * 16 + ar, (kk + 1) * 2 + ac16));
                #pragma unroll
                for (int nb = 0; nb < 4; nb++)
                    ldmx4(b_f[nxt][nb],
                          st + SM_B + sw128(warp_n * 64 + nb * 16 + br, (kk + 1) * 2 + bc16));
            }
            #pragma unroll
            for (int mi = 0; mi < 4; mi++) {
                #pragma unroll
                for (int ni = 0; ni < 8; ni++) {
                    const int nb = ni >> 1, hf = (ni & 1) * 2;
                    uint32_t b2[2] = {b_f[cur][nb][hf], b_f[cur][nb][hf + 1]};
                    mma16816(acc[mi][ni], a_f[cur][mi], b2);
                }
            }
        }
        slot = (slot + 1) % NSTAGE;
    }

    const int tr = lane >> 2;
    const int tc = (lane & 3) * 2;
    #pragma unroll
    for (int mi = 0; mi < 4; mi++) {
        const int r0 = bm + warp_m * 64 + mi * 16 + tr;
        #pragma unroll
        for (int ni = 0; ni < 8; ni++) {
            const int col = bn + warp_n * 64 + ni * 8 + tc;
            const float b0 = __ldg(&bias[col]);
            const float b1 = __ldg(&bias[col + 1]);
            float v00 = acc[mi][ni][0] + b0, v01 = acc[mi][ni][1] + b1;
            float v10 = acc[mi][ni][2] + b0, v11 = acc[mi][ni][3] + b1;
            if (sizeof(OutT) == 2) {
                *(__half2*)((__half*)C + (size_t)r0 * N + col) = __floats2half2_rn(v00, v01);
                *(__half2*)((__half*)C + (size_t)(r0 + 8) * N + col) = __floats2half2_rn(v10, v11);
            } else {
                *(float2*)((float*)C + (size_t)r0 * N + col) = make_float2(v00, v01);
                *(float2*)((float*)C + (size_t)(r0 + 8) * N + col) = make_float2(v10, v11);
            }
        }
    }
}

// ---------------------------------------------------------------------------
// Tensor-core attention: one block per (window b, head h), 128 threads (4 warps).
// (unchanged — this round measures it)
// ---------------------------------------------------------------------------
#define TQK 40    // half stride for q/k rows (80 B, conflict-free ldmatrix)
#define SCW 66    // f32 stride for score rows (264 B)
#define TPV 72    // half stride for p/vt rows (144 B, conflict-free ldmatrix)

__global__ __launch_bounds__(128) void attn_tc()
{
    __shared__ __half qs[64 * TQK];
    __shared__ __half ks[64 * TQK];
    __shared__ __half vt[32 * TPV];     // V^T: [c][l]
    __shared__ float  sc[64 * SCW];
    __shared__ __half ph[64 * TPV];     // unnormalized exp(P), fp16
    __shared__ float  inv_s[64];

    const int bh = blockIdx.x;
    const int b = bh >> 4, h = bh & 15, w = bh & (NMASK - 1);
    const int tid = threadIdx.x, lane = tid & 31, wid = tid >> 5;
    const float scale = 0.17677669529663687f;   // 1/sqrt(32)

    for (int i = tid; i < 64 * TPV / 2; i += 128)
        ((uint32_t*)ph)[i] = 0u;

    const __half2* qkv2 = (const __half2*)g_qkv_h;
    for (int t = tid; t < 49 * 16; t += 128) {
        int l = t >> 4, c2 = t & 15;
        size_t base = (size_t)(b * LTOK + l) * 768 + h * 16 + c2;
        *(__half2*)&qs[l * TQK + c2 * 2] = qkv2[base];
        *(__half2*)&ks[l * TQK + c2 * 2] = qkv2[base + 256];
    }
    for (int t = tid; t < 64 * 16; t += 128) {
        int l = t >> 4, c2 = t & 15;
        __half2 v = (l < 49) ? qkv2[(size_t)(b * LTOK + l) * 768 + h * 16 + 512 + c2]
                             : __floats2half2_rn(0.f, 0.f);
        vt[(c2 * 2 + 0) * TPV + l] = __low2half(v);
        vt[(c2 * 2 + 1) * TPV + l] = __high2half(v);
    }
    __syncthreads();

    const uint32_t sbq = smem_u32(qs), sbk = smem_u32(ks);
    const int ar = lane & 15;
    const int acolsel = (lane >> 4) << 4;
    const int br = (lane & 7) + ((lane >> 4) << 3);
    const int bcolsel = ((lane >> 3) & 1) << 4;

    float accs[8][4];
    #pragma unroll
    for (int ni = 0; ni < 8; ni++)
        #pragma unroll
        for (int e = 0; e < 4; e++) accs[ni][e] = 0.0f;

    #pragma unroll
    for (int kk = 0; kk < 2; kk++) {
        uint32_t af[4];
        ldmx4(af, sbq + (uint32_t)((wid * 16 + ar) * (TQK * 2) + kk * 32 + acolsel));
        uint32_t bf[4][4];
        #pragma unroll
        for (int nb = 0; nb < 4; nb++)
            ldmx4(bf[nb], sbk + (uint32_t)((nb * 16 + br) * (TQK * 2) + kk * 32 + bcolsel));
        #pragma unroll
        for (int ni = 0; ni < 8; ni++) {
            uint32_t b2[2] = {bf[ni >> 1][(ni & 1) * 2], bf[ni >> 1][(ni & 1) * 2 + 1]};
            mma16816(accs[ni], af, b2);
        }
    }

    const int tr = lane >> 2, tc = (lane & 3) * 2;
    #pragma unroll
    for (int ni = 0; ni < 8; ni++) {
        int r = wid * 16 + tr, col = ni * 8 + tc;
        *(float2*)&sc[r * SCW + col] = make_float2(accs[ni][0], accs[ni][1]);
        *(float2*)&sc[(r + 8) * SCW + col] = make_float2(accs[ni][2], accs[ni][3]);
    }
    __syncthreads();

    const float* crow = g_cbias + (size_t)w * LL;
    for (int i = wid; i < LTOK; i += 4) {
        float m = -1e30f;
        for (int j = lane; j < LTOK; j += 32) {
            float v = sc[i * SCW + j] * scale + __ldg(&crow[i * LTOK + j]);
            sc[i * SCW + j] = v;
            m = fmaxf(m, v);
        }
        #pragma unroll
        for (int o = 16; o; o >>= 1) m = fmaxf(m, __shfl_xor_sync(0xffffffffu, m, o));
        float sum = 0.0f;
        for (int j = lane; j < LTOK; j += 32) {
            float e = __expf(sc[i * SCW + j] - m);
            ph[i * TPV + j] = __float2half_rn(e);
            sum += e;
        }
        #pragma unroll
        for (int o = 16; o; o >>= 1) sum += __shfl_xor_sync(0xffffffffu, sum, o);
        if (lane == 0) inv_s[i] = 1.0f / sum;
    }
    __syncthreads();

    const uint32_t sbp = smem_u32(ph), sbv = smem_u32(vt);
    float acco[4][4];
    #pragma unroll
    for (int ni = 0; ni < 4; ni++)
        #pragma unroll
        for (int e = 0; e < 4; e++) acco[ni][e] = 0.0f;

    #pragma unroll
    for (int kk = 0; kk < 4; kk++) {
        uint32_t af[4];
        ldmx4(af, sbp + (uint32_t)((wid * 16 + ar) * (TPV * 2) + kk * 32 + acolsel));
        uint32_t bf[2][4];
        #pragma unroll
        for (int nb = 0; nb < 2; nb++)
            ldmx4(bf[nb], sbv + (uint32_t)((nb * 16 + br) * (TPV * 2) + kk * 32 + bcolsel));
        #pragma unroll
        for (int ni = 0; ni < 4; ni++) {
            uint32_t b2[2] = {bf[ni >> 1][(ni & 1) * 2], bf[ni >> 1][(ni & 1) * 2 + 1]};
            mma16816(acco[ni], af, b2);
        }
    }

    #pragma unroll
    for (int hr = 0; hr < 2; hr++) {
        int r = wid * 16 + tr + hr * 8;
        if (r < LTOK) {
            float is = inv_s[r];
            #pragma unroll
            for (int ni = 0; ni < 4; ni++) {
                int col = ni * 8 + tc;
                __half2 o = __floats2half2_rn(acco[ni][hr * 2] * is, acco[ni][hr * 2 + 1] * is);
                *(__half2*)&g_ctx_h[(size_t)(b * LTOK + r) * DMODEL + h * HDIM + col] = o;
            }
        }
    }
}

// ---------------------------------------------------------------------------
// Launch: prep_pre(0), prep_cbias(1), gemm1(2), attn(3)=capture, gemm2(4)
// ---------------------------------------------------------------------------
extern "C" void kernel_launch(void* const* d_in, const int* in_sizes, int n_in,
                              void* d_out, int out_size)
{
    const float* x          = (const float*)d_in[0];
    const float* w_qkv      = (const float*)d_in[1];
    const float* b_qkv      = (const float*)d_in[2];
    const float* w_out      = (const float*)d_in[3];
    const float* b_out      = (const float*)d_in[4];
    const float* bias_table = (const float*)d_in[5];
    const float* mask       = (const float*)d_in[6];
    const int*   rel_index  = (const int*)d_in[7];
    float*       out        = (float*)d_out;

    __half *qkvh, *xh, *ch, *wqh, *woh;
    cudaGetSymbolAddress((void**)&qkvh, g_qkv_h);
    cudaGetSymbolAddress((void**)&xh, g_x_h);
    cudaGetSymbolAddress((void**)&ch, g_ctx_h);
    cudaGetSymbolAddress((void**)&wqh, g_wqkvT_h);
    cudaGetSymbolAddress((void**)&woh, g_woutT_h);

    static bool attr_set = false;
    if (!attr_set) {
        cudaFuncSetAttribute(gemm_mma<__half>, cudaFuncAttributeMaxDynamicSharedMemorySize, SM_TOTAL);
        cudaFuncSetAttribute(gemm_mma<float>, cudaFuncAttributeMaxDynamicSharedMemorySize, SM_TOTAL);
        attr_set = true;
    }

    // slot 0: all fp16/transpose conversions in one kernel
    prep_pre<<<(PREP_TOTAL + 255) / 256, 256>>>(x, w_qkv, w_out, xh, wqh, woh);
    // slot 1: combined bias+mask table
    prep_cbias<<<(NMASK * LL + 255) / 256, 256>>>(bias_table, rel_index, mask);

    // slot 2: QKV projection (fp16 output)
    dim3 g1(N_QKV / GBN, MROWS / GBM);
    gemm_mma<__half><<<g1, 128, SM_TOTAL>>>(xh, wqh, b_qkv, qkvh, MROWS, N_QKV, DMODEL);

    // slot 3 (ncu capture slot): tensor-core attention
    attn_tc<<<BS * NHEAD, 128>>>();

    // slot 4: output projection (f32 output)
    dim3 g2(DMODEL / GBN, MROWS / GBM);
    gemm_mma<float><<<g2, 128, SM_TOTAL>>>(ch, woh, b_out, out, MROWS, DMODEL, DMODEL);
}

// round 15
// speedup vs baseline: 1.4777x; 1.4777x over previous
#include <cuda_runtime.h>
#include <cuda_fp16.h>
#include <math.h>
#include <stdint.h>

// Problem constants
#define BS     2048
#define LTOK   49
#define DMODEL 512
#define NHEAD  16
#define HDIM   32
#define NMASK  64
#define MROWS  (BS * LTOK)          // 100352
#define N_QKV  (3 * DMODEL)         // 1536
#define LL     (LTOK * LTOK)        // 2401

// Scratch (device globals: allocation-free per harness rules)
__device__ __half g_qkv_h[(size_t)MROWS * N_QKV];         // qkv as fp16
__device__ __half g_x_h[(size_t)MROWS * DMODEL];          // x as fp16
__device__ __half g_ctx_h[(size_t)MROWS * DMODEL];        // ctx as fp16
__device__ __half g_wqkvT_h[(size_t)N_QKV * DMODEL];      // W^T [N,K] fp16
__device__ __half g_woutT_h[(size_t)DMODEL * DMODEL];
__device__ float g_cbias[NMASK * LL];                     // combined relpos-bias + mask

// ---------------------------------------------------------------------------
// PTX helpers (sm_80-compatible: cp.async + ldmatrix + mma.sync only)
// ---------------------------------------------------------------------------
__device__ __forceinline__ uint32_t smem_u32(const void* p) {
    uint32_t a;
    asm("{ .reg .u64 t; cvta.to.shared.u64 t, %1; cvt.u32.u64 %0, t; }" : "=r"(a) : "l"(p));
    return a;
}
#define CP_ASYNC16(dst, src) \
    asm volatile("cp.async.cg.shared.global [%0], [%1], 16;" :: "r"(dst), "l"(src))
#define CP_COMMIT() asm volatile("cp.async.commit_group;" ::: "memory")
#define CP_WAIT(n)  asm volatile("cp.async.wait_group %0;" :: "n"(n) : "memory")

__device__ __forceinline__ void ldmx4(uint32_t* r, uint32_t addr) {
    asm volatile("ldmatrix.sync.aligned.m8n8.x4.shared.b16 {%0,%1,%2,%3}, [%4];"
                 : "=r"(r[0]), "=r"(r[1]), "=r"(r[2]), "=r"(r[3]) : "r"(addr));
}
__device__ __forceinline__ void mma16816(float* d, const uint32_t* a, const uint32_t* b) {
    asm volatile(
        "mma.sync.aligned.m16n8k16.row.col.f32.f16.f16.f32 "
        "{%0,%1,%2,%3}, {%4,%5,%6,%7}, {%8,%9}, {%0,%1,%2,%3};"
        : "+f"(d[0]), "+f"(d[1]), "+f"(d[2]), "+f"(d[3])
        : "r"(a[0]), "r"(a[1]), "r"(a[2]), "r"(a[3]), "r"(b[0]), "r"(b[1]));
}
__device__ __forceinline__ uint32_t pack_h2(float a, float b) {
    __half2 h = __floats2half2_rn(a, b);
    return *(uint32_t*)&h;
}

// SW128: 128-byte smem rows; 16B-chunk index XOR row&7 -> conflict-free
__device__ __forceinline__ uint32_t sw128(int row, int chunk16) {
    return (uint32_t)(row * 128 + ((chunk16 ^ (row & 7)) << 4));
}

// ---------------------------------------------------------------------------
// Prep kernels
// ---------------------------------------------------------------------------
#define XW4   (MROWS * DMODEL / 4)
#define WQKVN (N_QKV * DMODEL)
#define WOUTN (DMODEL * DMODEL)
#define PREP_TOTAL (XW4 + WQKVN + WOUTN)

__global__ void prep_pre(const float* __restrict__ x,
                         const float* __restrict__ w_qkv,
                         const float* __restrict__ w_out,
                         __half* __restrict__ xh,
                         __half* __restrict__ wqh,
                         __half* __restrict__ woh)
{
    int i = blockIdx.x * blockDim.x + threadIdx.x;
    if (i < XW4) {
        float4 v = ((const float4*)x)[i];
        ((__half2*)xh)[i * 2 + 0] = __floats2half2_rn(v.x, v.y);
        ((__half2*)xh)[i * 2 + 1] = __floats2half2_rn(v.z, v.w);
    } else if (i < XW4 + WQKVN) {
        int idx = i - XW4;
        int n = idx / DMODEL, k = idx - n * DMODEL;
        wqh[idx] = __float2half_rn(w_qkv[(size_t)k * N_QKV + n]);
    } else if (i < PREP_TOTAL) {
        int idx = i - XW4 - WQKVN;
        int n = idx / DMODEL, k = idx - n * DMODEL;
        woh[idx] = __float2half_rn(w_out[(size_t)k * DMODEL + n]);
    }
}

__global__ void prep_cbias(const float* __restrict__ bias_table,
                           const int* __restrict__ rel_index,
                           const float* __restrict__ mask)
{
    int i = blockIdx.x * blockDim.x + threadIdx.x;
    if (i >= NMASK * LL) return;
    int w = i / LL, idx = i - w * LL;
    int h = w & 15;
    g_cbias[i] = bias_table[rel_index[idx] * NHEAD + h] + mask[(size_t)w * LL + idx];
}

// ---------------------------------------------------------------------------
// mma.sync GEMM (unchanged from R10 best): 128x128 tile, BK=64, 4 warps,
// 3-stage cp.async, fragment double-buffering, 2 CTA/SM.
// ---------------------------------------------------------------------------
#define GBM 128
#define GBN 128
#define GBK 64
#define TILEB (128 * 128)
#define STAGEB (2 * TILEB)
#define NSTAGE 3
#define SM_A 0
#define SM_B TILEB
#define SM_TOTAL (NSTAGE * STAGEB)      // 98304

template <typename OutT>
__global__ __launch_bounds__(128, 2) void gemm_mma(
    const __half* __restrict__ A, const __half* __restrict__ B,
    const float* __restrict__ bias, OutT* __restrict__ C,
    int M, int N, int K)
{
    extern __shared__ char smem[];
    const uint32_t sbase = smem_u32(smem);
    const int tid = threadIdx.x;
    const int lane = tid & 31;
    const int wid = tid >> 5;
    const int warp_m = wid & 1;
    const int warp_n = wid >> 1;
    const int bm = blockIdx.y * GBM;
    const int bn = blockIdx.x * GBN;

    float acc[4][8][4];
    #pragma unroll
    for (int mi = 0; mi < 4; mi++)
        #pragma unroll
        for (int ni = 0; ni < 8; ni++)
            #pragma unroll
            for (int e = 0; e < 4; e++) acc[mi][ni][e] = 0.0f;

    const int nch = K / GBK;

    auto load_stage = [&](int ch, int s) {
        const int k0 = ch * GBK;
        const uint32_t stbase = sbase + (uint32_t)s * STAGEB;
        #pragma unroll
        for (int i = 0; i < 8; i++) {
            int u = tid + i * 128;
            int row = u >> 3, c16 = u & 7;
            const void* srcA = A + (size_t)(bm + row) * K + k0 + c16 * 8;
            CP_ASYNC16(stbase + SM_A + sw128(row, c16), srcA);
            const void* srcB = B + (size_t)(bn + row) * K + k0 + c16 * 8;
            CP_ASYNC16(stbase + SM_B + sw128(row, c16), srcB);
        }
        CP_COMMIT();
    };

    load_stage(0, 0);
    load_stage(1, 1);

    uint32_t a_f[2][4][4], b_f[2][4][4];
    const int ar = lane & 15;
    const int ac16 = (lane >> 4);
    const int br = (lane & 7) + ((lane >> 4) << 3);
    const int bc16 = ((lane >> 3) & 1);

    int slot = 0;
    for (int ch = 0; ch < nch; ch++) {
        if (ch + 1 < nch) { CP_WAIT(1); } else { CP_WAIT(0); }
        __syncthreads();
        if (ch + 2 < nch) load_stage(ch + 2, (slot + 2) % NSTAGE);

        const uint32_t st = sbase + (uint32_t)slot * STAGEB;

        #pragma unroll
        for (int mi = 0; mi < 4; mi++)
            ldmx4(a_f[0][mi], st + SM_A + sw128(warp_m * 64 + mi * 16 + ar, ac16));
        #pragma unroll
        for (int nb = 0; nb < 4; nb++)
            ldmx4(b_f[0][nb], st + SM_B + sw128(warp_n * 64 + nb * 16 + br, bc16));

        #pragma unroll
        for (int kk = 0; kk < 4; kk++) {
            const int cur = kk & 1, nxt = cur ^ 1;
            if (kk < 3) {
                #pragma unroll
                for (int mi = 0; mi < 4; mi++)
                    ldmx4(a_f[nxt][mi],
                          st + SM_A + sw128(warp_m * 64 + mi * 16 + ar, (kk + 1) * 2 + ac16));
                #pragma unroll
                for (int nb = 0; nb < 4; nb++)
                    ldmx4(b_f[nxt][nb],
                          st + SM_B + sw128(warp_n * 64 + nb * 16 + br, (kk + 1) * 2 + bc16));
            }
            #pragma unroll
            for (int mi = 0; mi < 4; mi++) {
                #pragma unroll
                for (int ni = 0; ni < 8; ni++) {
                    const int nb = ni >> 1, hf = (ni & 1) * 2;
                    uint32_t b2[2] = {b_f[cur][nb][hf], b_f[cur][nb][hf + 1]};
                    mma16816(acc[mi][ni], a_f[cur][mi], b2);
                }
            }
        }
        slot = (slot + 1) % NSTAGE;
    }

    const int tr = lane >> 2;
    const int tc = (lane & 3) * 2;
    #pragma unroll
    for (int mi = 0; mi < 4; mi++) {
        const int r0 = bm + warp_m * 64 + mi * 16 + tr;
        #pragma unroll
        for (int ni = 0; ni < 8; ni++) {
            const int col = bn + warp_n * 64 + ni * 8 + tc;
            const float b0 = __ldg(&bias[col]);
            const float b1 = __ldg(&bias[col + 1]);
            float v00 = acc[mi][ni][0] + b0, v01 = acc[mi][ni][1] + b1;
            float v10 = acc[mi][ni][2] + b0, v11 = acc[mi][ni][3] + b1;
            if (sizeof(OutT) == 2) {
                *(__half2*)((__half*)C + (size_t)r0 * N + col) = __floats2half2_rn(v00, v01);
                *(__half2*)((__half*)C + (size_t)(r0 + 8) * N + col) = __floats2half2_rn(v10, v11);
            } else {
                *(float2*)((float*)C + (size_t)r0 * N + col) = make_float2(v00, v01);
                *(float2*)((float*)C + (size_t)(r0 + 8) * N + col) = make_float2(v10, v11);
            }
        }
    }
}

// ---------------------------------------------------------------------------
// Register-resident TC attention: one block per (window b, head h), 128 thr.
// S fragments stay in registers; softmax + P-fragment build all in regs.
// Smem: q/k tiles (ldmatrix source) + V^T only (~15KB). One __syncthreads.
// ---------------------------------------------------------------------------
#define TQK 40    // half stride for q/k rows (80 B, conflict-free ldmatrix)
#define TPV 72    // half stride for vt rows (144 B, conflict-free ldmatrix)

__global__ __launch_bounds__(128, 5) void attn_tc()
{
    __shared__ __half qs[64 * TQK];
    __shared__ __half ks[64 * TQK];
    __shared__ __half vt[32 * TPV];     // V^T: [c][l]

    const int bh = blockIdx.x;
    const int b = bh >> 4, h = bh & 15, w = bh & (NMASK - 1);
    const int tid = threadIdx.x, lane = tid & 31, wid = tid >> 5;
    const float scale = 0.17677669529663687f;   // 1/sqrt(32)

    // load q, k (rows < 49) and v^T (zero-padded)
    const __half2* qkv2 = (const __half2*)g_qkv_h;
    for (int t = tid; t < 49 * 16; t += 128) {
        int l = t >> 4, c2 = t & 15;
        size_t base = (size_t)(b * LTOK + l) * 768 + h * 16 + c2;
        *(__half2*)&qs[l * TQK + c2 * 2] = qkv2[base];
        *(__half2*)&ks[l * TQK + c2 * 2] = qkv2[base + 256];
    }
    for (int t = tid; t < 64 * 16; t += 128) {
        int l = t >> 4, c2 = t & 15;
        __half2 v = (l < 49) ? qkv2[(size_t)(b * LTOK + l) * 768 + h * 16 + 512 + c2]
                             : __floats2half2_rn(0.f, 0.f);
        vt[(c2 * 2 + 0) * TPV + l] = __low2half(v);
        vt[(c2 * 2 + 1) * TPV + l] = __high2half(v);
    }
    __syncthreads();

    // ---- S = Q K^T (warp = 16-row slab), M=N=64, K=32, accum in regs
    const uint32_t sbq = smem_u32(qs), sbk = smem_u32(ks);
    const int ar = lane & 15;
    const int acolsel = (lane >> 4) << 4;
    const int br = (lane & 7) + ((lane >> 4) << 3);
    const int bcolsel = ((lane >> 3) & 1) << 4;

    float accs[8][4];
    #pragma unroll
    for (int ni = 0; ni < 8; ni++)
        #pragma unroll
        for (int e = 0; e < 4; e++) accs[ni][e] = 0.0f;

    #pragma unroll
    for (int kk = 0; kk < 2; kk++) {
        uint32_t af[4];
        ldmx4(af, sbq + (uint32_t)((wid * 16 + ar) * (TQK * 2) + kk * 32 + acolsel));
        uint32_t bf[4][4];
        #pragma unroll
        for (int nb = 0; nb < 4; nb++)
            ldmx4(bf[nb], sbk + (uint32_t)((nb * 16 + br) * (TQK * 2) + kk * 32 + bcolsel));
        #pragma unroll
        for (int ni = 0; ni < 8; ni++) {
            uint32_t b2[2] = {bf[ni >> 1][(ni & 1) * 2], bf[ni >> 1][(ni & 1) * 2 + 1]};
            mma16816(accs[ni], af, b2);
        }
    }

    // ---- softmax fully in registers
    const int tr = lane >> 2, tc = (lane & 3) * 2;
    const int row0 = wid * 16 + tr;      // e0,e1
    const int row1 = row0 + 8;           // e2,e3
    const float* crow = g_cbias + (size_t)w * LL;

    float m0 = -1e30f, m1 = -1e30f;
    #pragma unroll
    for (int ni = 0; ni < 8; ni++) {
        #pragma unroll
        for (int e = 0; e < 4; e++) {
            const int row = (e < 2) ? row0 : row1;
            const int col = ni * 8 + tc + (e & 1);
            float v = -1e30f;
            if (row < LTOK && col < LTOK)
                v = accs[ni][e] * scale + __ldg(&crow[row * LTOK + col]);
            accs[ni][e] = v;
            if (e < 2) m0 = fmaxf(m0, v); else m1 = fmaxf(m1, v);
        }
    }
    #pragma unroll
    for (int o = 1; o <= 2; o <<= 1) {
        m0 = fmaxf(m0, __shfl_xor_sync(0xffffffffu, m0, o));
        m1 = fmaxf(m1, __shfl_xor_sync(0xffffffffu, m1, o));
    }
    float s0 = 0.0f, s1 = 0.0f;
    #pragma unroll
    for (int ni = 0; ni < 8; ni++) {
        #pragma unroll
        for (int e = 0; e < 4; e++) {
            float ex = __expf(accs[ni][e] - ((e < 2) ? m0 : m1));
            accs[ni][e] = ex;
            if (e < 2) s0 += ex; else s1 += ex;
        }
    }
    #pragma unroll
    for (int o = 1; o <= 2; o <<= 1) {
        s0 += __shfl_xor_sync(0xffffffffu, s0, o);
        s1 += __shfl_xor_sync(0xffffffffu, s1, o);
    }
    const float inv0 = 1.0f / s0, inv1 = 1.0f / s1;

    // build normalized P fragments directly (C-frag -> A-frag mapping)
    uint32_t ap[4][4];
    #pragma unroll
    for (int kk = 0; kk < 4; kk++) {
        ap[kk][0] = pack_h2(accs[2 * kk][0] * inv0, accs[2 * kk][1] * inv0);
        ap[kk][1] = pack_h2(accs[2 * kk][2] * inv1, accs[2 * kk][3] * inv1);
        ap[kk][2] = pack_h2(accs[2 * kk + 1][0] * inv0, accs[2 * kk + 1][1] * inv0);
        ap[kk][3] = pack_h2(accs[2 * kk + 1][2] * inv1, accs[2 * kk + 1][3] * inv1);
    }

    // ---- O = P V (M=64, N=32, K=64), A from registers, B from vt smem
    const uint32_t sbv = smem_u32(vt);
    float acco[4][4];
    #pragma unroll
    for (int ni = 0; ni < 4; ni++)
        #pragma unroll
        for (int e = 0; e < 4; e++) acco[ni][e] = 0.0f;

    #pragma unroll
    for (int kk = 0; kk < 4; kk++) {
        uint32_t bf[2][4];
        #pragma unroll
        for (int nb = 0; nb < 2; nb++)
            ldmx4(bf[nb], sbv + (uint32_t)((nb * 16 + br) * (TPV * 2) + kk * 32 + bcolsel));
        #pragma unroll
        for (int ni = 0; ni < 4; ni++) {
            uint32_t b2[2] = {bf[ni >> 1][(ni & 1) * 2], bf[ni >> 1][(ni & 1) * 2 + 1]};
            mma16816(acco[ni], ap[kk], b2);
        }
    }

    // store ctx fp16 (already normalized)
    if (row0 < LTOK) {
        #pragma unroll
        for (int ni = 0; ni < 4; ni++) {
            int col = ni * 8 + tc;
            *(__half2*)&g_ctx_h[(size_t)(b * LTOK + row0) * DMODEL + h * HDIM + col] =
                __floats2half2_rn(acco[ni][0], acco[ni][1]);
        }
    }
    if (row1 < LTOK) {
        #pragma unroll
        for (int ni = 0; ni < 4; ni++) {
            int col = ni * 8 + tc;
            *(__half2*)&g_ctx_h[(size_t)(b * LTOK + row1) * DMODEL + h * HDIM + col] =
                __floats2half2_rn(acco[ni][2], acco[ni][3]);
        }
    }
}

// ---------------------------------------------------------------------------
// Launch: prep_pre(0), prep_cbias(1), gemm1(2), attn(3)=capture, gemm2(4)
// ---------------------------------------------------------------------------
extern "C" void kernel_launch(void* const* d_in, const int* in_sizes, int n_in,
                              void* d_out, int out_size)
{
    const float* x          = (const float*)d_in[0];
    const float* w_qkv      = (const float*)d_in[1];
    const float* b_qkv      = (const float*)d_in[2];
    const float* w_out      = (const float*)d_in[3];
    const float* b_out      = (const float*)d_in[4];
    const float* bias_table = (const float*)d_in[5];
    const float* mask       = (const float*)d_in[6];
    const int*   rel_index  = (const int*)d_in[7];
    float*       out        = (float*)d_out;

    __half *qkvh, *xh, *ch, *wqh, *woh;
    cudaGetSymbolAddress((void**)&qkvh, g_qkv_h);
    cudaGetSymbolAddress((void**)&xh, g_x_h);
    cudaGetSymbolAddress((void**)&ch, g_ctx_h);
    cudaGetSymbolAddress((void**)&wqh, g_wqkvT_h);
    cudaGetSymbolAddress((void**)&woh, g_woutT_h);

    static bool attr_set = false;
    if (!attr_set) {
        cudaFuncSetAttribute(gemm_mma<__half>, cudaFuncAttributeMaxDynamicSharedMemorySize, SM_TOTAL);
        cudaFuncSetAttribute(gemm_mma<float>, cudaFuncAttributeMaxDynamicSharedMemorySize, SM_TOTAL);
        attr_set = true;
    }

    prep_pre<<<(PREP_TOTAL + 255) / 256, 256>>>(x, w_qkv, w_out, xh, wqh, woh);
    prep_cbias<<<(NMASK * LL + 255) / 256, 256>>>(bias_table, rel_index, mask);

    dim3 g1(N_QKV / GBN, MROWS / GBM);
    gemm_mma<__half><<<g1, 128, SM_TOTAL>>>(xh, wqh, b_qkv, qkvh, MROWS, N_QKV, DMODEL);

    // slot 3 (ncu capture slot): register-resident attention
    attn_tc<<<BS * NHEAD, 128>>>();

    dim3 g2(DMODEL / GBN, MROWS / GBM);
    gemm_mma<float><<<g2, 128, SM_TOTAL>>>(ch, woh, b_out, out, MROWS, DMODEL, DMODEL);
}

// round 16
// speedup vs baseline: 1.7484x; 1.1832x over previous
#include <cuda_runtime.h>
#include <cuda_fp16.h>
#include <math.h>
#include <stdint.h>

// Problem constants
#define BS     2048
#define LTOK   49
#define DMODEL 512
#define NHEAD  16
#define HDIM   32
#define NMASK  64
#define MROWS  (BS * LTOK)          // 100352
#define N_QKV  (3 * DMODEL)         // 1536
#define LL     (LTOK * LTOK)        // 2401
#define CBSTR  2404                 // padded floats per window (16B-aligned rows)

// Scratch (device globals: allocation-free per harness rules)
__device__ __half g_qkv_h[(size_t)MROWS * N_QKV];
__device__ __half g_x_h[(size_t)MROWS * DMODEL];
__device__ __half g_ctx_h[(size_t)MROWS * DMODEL];
__device__ __half g_wqkvT_h[(size_t)N_QKV * DMODEL];
__device__ __half g_woutT_h[(size_t)DMODEL * DMODEL];
__device__ float g_cbias[NMASK * CBSTR];                  // combined bias+mask, padded

// ---------------------------------------------------------------------------
// PTX helpers
// ---------------------------------------------------------------------------
__device__ __forceinline__ uint32_t smem_u32(const void* p) {
    uint32_t a;
    asm("{ .reg .u64 t; cvta.to.shared.u64 t, %1; cvt.u32.u64 %0, t; }" : "=r"(a) : "l"(p));
    return a;
}
#define CP_ASYNC16(dst, src) \
    asm volatile("cp.async.cg.shared.global [%0], [%1], 16;" :: "r"(dst), "l"(src))
#define CP_COMMIT() asm volatile("cp.async.commit_group;" ::: "memory")
#define CP_WAIT(n)  asm volatile("cp.async.wait_group %0;" :: "n"(n) : "memory")

__device__ __forceinline__ void ldmx4(uint32_t* r, uint32_t addr) {
    asm volatile("ldmatrix.sync.aligned.m8n8.x4.shared.b16 {%0,%1,%2,%3}, [%4];"
                 : "=r"(r[0]), "=r"(r[1]), "=r"(r[2]), "=r"(r[3]) : "r"(addr));
}
__device__ __forceinline__ void mma16816(float* d, const uint32_t* a, const uint32_t* b) {
    asm volatile(
        "mma.sync.aligned.m16n8k16.row.col.f32.f16.f16.f32 "
        "{%0,%1,%2,%3}, {%4,%5,%6,%7}, {%8,%9}, {%0,%1,%2,%3};"
        : "+f"(d[0]), "+f"(d[1]), "+f"(d[2]), "+f"(d[3])
        : "r"(a[0]), "r"(a[1]), "r"(a[2]), "r"(a[3]), "r"(b[0]), "r"(b[1]));
}
__device__ __forceinline__ uint32_t pack_h2(float a, float b) {
    __half2 h = __floats2half2_rn(a, b);
    return *(uint32_t*)&h;
}
__device__ __forceinline__ uint32_t sw128(int row, int chunk16) {
    return (uint32_t)(row * 128 + ((chunk16 ^ (row & 7)) << 4));
}

// ---------------------------------------------------------------------------
// Prep kernels
// ---------------------------------------------------------------------------
#define XW4   (MROWS * DMODEL / 4)
#define WQKVN (N_QKV * DMODEL)
#define WOUTN (DMODEL * DMODEL)
#define PREP_TOTAL (XW4 + WQKVN + WOUTN)

__global__ void prep_pre(const float* __restrict__ x,
                         const float* __restrict__ w_qkv,
                         const float* __restrict__ w_out,
                         __half* __restrict__ xh,
                         __half* __restrict__ wqh,
                         __half* __restrict__ woh)
{
    int i = blockIdx.x * blockDim.x + threadIdx.x;
    if (i < XW4) {
        float4 v = ((const float4*)x)[i];
        ((__half2*)xh)[i * 2 + 0] = __floats2half2_rn(v.x, v.y);
        ((__half2*)xh)[i * 2 + 1] = __floats2half2_rn(v.z, v.w);
    } else if (i < XW4 + WQKVN) {
        int idx = i - XW4;
        int n = idx / DMODEL, k = idx - n * DMODEL;
        wqh[idx] = __float2half_rn(w_qkv[(size_t)k * N_QKV + n]);
    } else if (i < PREP_TOTAL) {
        int idx = i - XW4 - WQKVN;
        int n = idx / DMODEL, k = idx - n * DMODEL;
        woh[idx] = __float2half_rn(w_out[(size_t)k * DMODEL + n]);
    }
}

__global__ void prep_cbias(const float* __restrict__ bias_table,
                           const int* __restrict__ rel_index,
                           const float* __restrict__ mask)
{
    int i = blockIdx.x * blockDim.x + threadIdx.x;
    if (i >= NMASK * LL) return;
    int w = i / LL, idx = i - w * LL;
    int h = w & 15;
    g_cbias[(size_t)w * CBSTR + idx] =
        bias_table[rel_index[idx] * NHEAD + h] + mask[(size_t)w * LL + idx];
}

// ---------------------------------------------------------------------------
// mma.sync GEMM (unchanged best): 128x128 tile, BK=64, 4 warps,
// 3-stage cp.async, fragment double-buffering, 2 CTA/SM.
// ---------------------------------------------------------------------------
#define GBM 128
#define GBN 128
#define GBK 64
#define TILEB (128 * 128)
#define STAGEB (2 * TILEB)
#define NSTAGE 3
#define SM_A 0
#define SM_B TILEB
#define SM_TOTAL (NSTAGE * STAGEB)      // 98304

template <typename OutT>
__global__ __launch_bounds__(128, 2) void gemm_mma(
    const __half* __restrict__ A, const __half* __restrict__ B,
    const float* __restrict__ bias, OutT* __restrict__ C,
    int M, int N, int K)
{
    extern __shared__ char smem[];
    const uint32_t sbase = smem_u32(smem);
    const int tid = threadIdx.x;
    const int lane = tid & 31;
    const int wid = tid >> 5;
    const int warp_m = wid & 1;
    const int warp_n = wid >> 1;
    const int bm = blockIdx.y * GBM;
    const int bn = blockIdx.x * GBN;

    float acc[4][8][4];
    #pragma unroll
    for (int mi = 0; mi < 4; mi++)
        #pragma unroll
        for (int ni = 0; ni < 8; ni++)
            #pragma unroll
            for (int e = 0; e < 4; e++) acc[mi][ni][e] = 0.0f;

    const int nch = K / GBK;

    auto load_stage = [&](int ch, int s) {
        const int k0 = ch * GBK;
        const uint32_t stbase = sbase + (uint32_t)s * STAGEB;
        #pragma unroll
        for (int i = 0; i < 8; i++) {
            int u = tid + i * 128;
            int row = u >> 3, c16 = u & 7;
            const void* srcA = A + (size_t)(bm + row) * K + k0 + c16 * 8;
            CP_ASYNC16(stbase + SM_A + sw128(row, c16), srcA);
            const void* srcB = B + (size_t)(bn + row) * K + k0 + c16 * 8;
            CP_ASYNC16(stbase + SM_B + sw128(row, c16), srcB);
        }
        CP_COMMIT();
    };

    load_stage(0, 0);
    load_stage(1, 1);

    uint32_t a_f[2][4][4], b_f[2][4][4];
    const int ar = lane & 15;
    const int ac16 = (lane >> 4);
    const int br = (lane & 7) + ((lane >> 4) << 3);
    const int bc16 = ((lane >> 3) & 1);

    int slot = 0;
    for (int ch = 0; ch < nch; ch++) {
        if (ch + 1 < nch) { CP_WAIT(1); } else { CP_WAIT(0); }
        __syncthreads();
        if (ch + 2 < nch) load_stage(ch + 2, (slot + 2) % NSTAGE);

        const uint32_t st = sbase + (uint32_t)slot * STAGEB;

        #pragma unroll
        for (int mi = 0; mi < 4; mi++)
            ldmx4(a_f[0][mi], st + SM_A + sw128(warp_m * 64 + mi * 16 + ar, ac16));
        #pragma unroll
        for (int nb = 0; nb < 4; nb++)
            ldmx4(b_f[0][nb], st + SM_B + sw128(warp_n * 64 + nb * 16 + br, bc16));

        #pragma unroll
        for (int kk = 0; kk < 4; kk++) {
            const int cur = kk & 1, nxt = cur ^ 1;
            if (kk < 3) {
                #pragma unroll
                for (int mi = 0; mi < 4; mi++)
                    ldmx4(a_f[nxt][mi],
                          st + SM_A + sw128(warp_m * 64 + mi * 16 + ar, (kk + 1) * 2 + ac16));
                #pragma unroll
                for (int nb = 0; nb < 4; nb++)
                    ldmx4(b_f[nxt][nb],
                          st + SM_B + sw128(warp_n * 64 + nb * 16 + br, (kk + 1) * 2 + bc16));
            }
            #pragma unroll
            for (int mi = 0; mi < 4; mi++) {
                #pragma unroll
                for (int ni = 0; ni < 8; ni++) {
                    const int nb = ni >> 1, hf = (ni & 1) * 2;
                    uint32_t b2[2] = {b_f[cur][nb][hf], b_f[cur][nb][hf + 1]};
                    mma16816(acc[mi][ni], a_f[cur][mi], b2);
                }
            }
        }
        slot = (slot + 1) % NSTAGE;
    }

    const int tr = lane >> 2;
    const int tc = (lane & 3) * 2;
    #pragma unroll
    for (int mi = 0; mi < 4; mi++) {
        const int r0 = bm + warp_m * 64 + mi * 16 + tr;
        #pragma unroll
        for (int ni = 0; ni < 8; ni++) {
            const int col = bn + warp_n * 64 + ni * 8 + tc;
            const float b0 = __ldg(&bias[col]);
            const float b1 = __ldg(&bias[col + 1]);
            float v00 = acc[mi][ni][0] + b0, v01 = acc[mi][ni][1] + b1;
            float v10 = acc[mi][ni][2] + b0, v11 = acc[mi][ni][3] + b1;
            if (sizeof(OutT) == 2) {
                *(__half2*)((__half*)C + (size_t)r0 * N + col) = __floats2half2_rn(v00, v01);
                *(__half2*)((__half*)C + (size_t)(r0 + 8) * N + col) = __floats2half2_rn(v10, v11);
            } else {
                *(float2*)((float*)C + (size_t)r0 * N + col) = make_float2(v00, v01);
                *(float2*)((float*)C + (size_t)(r0 + 8) * N + col) = make_float2(v10, v11);
            }
        }
    }
}

// ---------------------------------------------------------------------------
// Register-resident TC attention v2: cp.async streamed q/k + cbias window,
// softmax reads cbias from smem. One sync. 6 CTAs/SM target.
// ---------------------------------------------------------------------------
#define TQK 40    // half stride for q/k rows (80 B, conflict-free ldmatrix)
#define TPV 72    // half stride for vt rows (144 B, conflict-free ldmatrix)

__global__ __launch_bounds__(128, 6) void attn_tc()
{
    __shared__ __half qs[64 * TQK];
    __shared__ __half ks[64 * TQK];
    __shared__ __half vt[32 * TPV];     // V^T: [c][l]
    __shared__ float  cbs[CBSTR];       // this window's bias+mask (9616 B)

    const int bh = blockIdx.x;
    const int b = bh >> 4, h = bh & 15, w = bh & (NMASK - 1);
    const int tid = threadIdx.x, lane = tid & 31, wid = tid >> 5;
    const float scale = 0.17677669529663687f;   // 1/sqrt(32)

    const uint32_t sbq = smem_u32(qs), sbk = smem_u32(ks);
    const uint32_t sbv = smem_u32(vt), sbc = smem_u32(cbs);

    // --- stream cbias window: 601 x 16B coalesced cp.async
    {
        const char* src = (const char*)(g_cbias + (size_t)w * CBSTR);
        for (int t = tid; t < CBSTR / 4; t += 128)
            CP_ASYNC16(sbc + t * 16, src + t * 16);
    }
    // --- stream q, k rows: 49 rows x 4 chunks x 2 tensors
    {
        const char* base = (const char*)g_qkv_h;
        for (int t = tid; t < 49 * 4; t += 128) {
            int l = t >> 2, c = t & 3;
            size_t rowh = (size_t)(b * LTOK + l) * 1536 + h * 32;  // half index
            CP_ASYNC16(sbq + l * (TQK * 2) + c * 16, base + rowh * 2 + c * 16);
            CP_ASYNC16(sbk + l * (TQK * 2) + c * 16, base + (rowh + 512) * 2 + c * 16);
        }
    }
    CP_COMMIT();

    // --- v load + register transpose (overlaps with cp.async DMA)
    const __half2* qkv2 = (const __half2*)g_qkv_h;
    for (int t = tid; t < 64 * 16; t += 128) {
        int l = t >> 4, c2 = t & 15;
        __half2 v = (l < 49) ? qkv2[(size_t)(b * LTOK + l) * 768 + h * 16 + 512 + c2]
                             : __floats2half2_rn(0.f, 0.f);
        vt[(c2 * 2 + 0) * TPV + l] = __low2half(v);
        vt[(c2 * 2 + 1) * TPV + l] = __high2half(v);
    }
    CP_WAIT(0);
    __syncthreads();

    // ---- S = Q K^T (warp = 16-row slab), M=N=64, K=32, accum in regs
    const int ar = lane & 15;
    const int acolsel = (lane >> 4) << 4;
    const int br = (lane & 7) + ((lane >> 4) << 3);
    const int bcolsel = ((lane >> 3) & 1) << 4;

    float accs[8][4];
    #pragma unroll
    for (int ni = 0; ni < 8; ni++)
        #pragma unroll
        for (int e = 0; e < 4; e++) accs[ni][e] = 0.0f;

    #pragma unroll
    for (int kk = 0; kk < 2; kk++) {
        uint32_t af[4];
        ldmx4(af, sbq + (uint32_t)((wid * 16 + ar) * (TQK * 2) + kk * 32 + acolsel));
        uint32_t bf[4][4];
        #pragma unroll
        for (int nb = 0; nb < 4; nb++)
            ldmx4(bf[nb], sbk + (uint32_t)((nb * 16 + br) * (TQK * 2) + kk * 32 + bcolsel));
        #pragma unroll
        for (int ni = 0; ni < 8; ni++) {
            uint32_t b2[2] = {bf[ni >> 1][(ni & 1) * 2], bf[ni >> 1][(ni & 1) * 2 + 1]};
            mma16816(accs[ni], af, b2);
        }
    }

    // ---- softmax fully in registers, bias from smem
    const int tr = lane >> 2, tc = (lane & 3) * 2;
    const int row0 = wid * 16 + tr;      // e0,e1
    const int row1 = row0 + 8;           // e2,e3

    float m0 = -1e30f, m1 = -1e30f;
    #pragma unroll
    for (int ni = 0; ni < 8; ni++) {
        #pragma unroll
        for (int e = 0; e < 4; e++) {
            const int row = (e < 2) ? row0 : row1;
            const int col = ni * 8 + tc + (e & 1);
            float v = -1e30f;
            if (row < LTOK && col < LTOK)
                v = accs[ni][e] * scale + cbs[row * LTOK + col];
            accs[ni][e] = v;
            if (e < 2) m0 = fmaxf(m0, v); else m1 = fmaxf(m1, v);
        }
    }
    #pragma unroll
    for (int o = 1; o <= 2; o <<= 1) {
        m0 = fmaxf(m0, __shfl_xor_sync(0xffffffffu, m0, o));
        m1 = fmaxf(m1, __shfl_xor_sync(0xffffffffu, m1, o));
    }
    float s0 = 0.0f, s1 = 0.0f;
    #pragma unroll
    for (int ni = 0; ni < 8; ni++) {
        #pragma unroll
        for (int e = 0; e < 4; e++) {
            float ex = __expf(accs[ni][e] - ((e < 2) ? m0 : m1));
            accs[ni][e] = ex;
            if (e < 2) s0 += ex; else s1 += ex;
        }
    }
    #pragma unroll
    for (int o = 1; o <= 2; o <<= 1) {
        s0 += __shfl_xor_sync(0xffffffffu, s0, o);
        s1 += __shfl_xor_sync(0xffffffffu, s1, o);
    }
    const float inv0 = 1.0f / s0, inv1 = 1.0f / s1;

    // build normalized P fragments directly (C-frag -> A-frag mapping)
    uint32_t ap[4][4];
    #pragma unroll
    for (int kk = 0; kk < 4; kk++) {
        ap[kk][0] = pack_h2(accs[2 * kk][0] * inv0, accs[2 * kk][1] * inv0);
        ap[kk][1] = pack_h2(accs[2 * kk][2] * inv1, accs[2 * kk][3] * inv1);
        ap[kk][2] = pack_h2(accs[2 * kk + 1][0] * inv0, accs[2 * kk + 1][1] * inv0);
        ap[kk][3] = pack_h2(accs[2 * kk + 1][2] * inv1, accs[2 * kk + 1][3] * inv1);
    }

    // ---- O = P V (M=64, N=32, K=64), A from registers, B from vt smem
    float acco[4][4];
    #pragma unroll
    for (int ni = 0; ni < 4; ni++)
        #pragma unroll
        for (int e = 0; e < 4; e++) acco[ni][e] = 0.0f;

    #pragma unroll
    for (int kk = 0; kk < 4; kk++) {
        uint32_t bf[2][4];
        #pragma unroll
        for (int nb = 0; nb < 2; nb++)
            ldmx4(bf[nb], sbv + (uint32_t)((nb * 16 + br) * (TPV * 2) + kk * 32 + bcolsel));
        #pragma unroll
        for (int ni = 0; ni < 4; ni++) {
            uint32_t b2[2] = {bf[ni >> 1][(ni & 1) * 2], bf[ni >> 1][(ni & 1) * 2 + 1]};
            mma16816(acco[ni], ap[kk], b2);
        }
    }

    // store ctx fp16 (already normalized)
    if (row0 < LTOK) {
        #pragma unroll
        for (int ni = 0; ni < 4; ni++) {
            int col = ni * 8 + tc;
            *(__half2*)&g_ctx_h[(size_t)(b * LTOK + row0) * DMODEL + h * HDIM + col] =
                __floats2half2_rn(acco[ni][0], acco[ni][1]);
        }
    }
    if (row1 < LTOK) {
        #pragma unroll
        for (int ni = 0; ni < 4; ni++) {
            int col = ni * 8 + tc;
            *(__half2*)&g_ctx_h[(size_t)(b * LTOK + row1) * DMODEL + h * HDIM + col] =
                __floats2half2_rn(acco[ni][2], acco[ni][3]);
        }
    }
}

// ---------------------------------------------------------------------------
// Launch: prep_pre(0), prep_cbias(1), gemm1(2), attn(3)=capture, gemm2(4)
// ---------------------------------------------------------------------------
extern "C" void kernel_launch(void* const* d_in, const int* in_sizes, int n_in,
                              void* d_out, int out_size)
{
    const float* x          = (const float*)d_in[0];
    const float* w_qkv      = (const float*)d_in[1];
    const float* b_qkv      = (const float*)d_in[2];
    const float* w_out      = (const float*)d_in[3];
    const float* b_out      = (const float*)d_in[4];
    const float* bias_table = (const float*)d_in[5];
    const float* mask       = (const float*)d_in[6];
    const int*   rel_index  = (const int*)d_in[7];
    float*       out        = (float*)d_out;

    __half *qkvh, *xh, *ch, *wqh, *woh;
    cudaGetSymbolAddress((void**)&qkvh, g_qkv_h);
    cudaGetSymbolAddress((void**)&xh, g_x_h);
    cudaGetSymbolAddress((void**)&ch, g_ctx_h);
    cudaGetSymbolAddress((void**)&wqh, g_wqkvT_h);
    cudaGetSymbolAddress((void**)&woh, g_woutT_h);

    static bool attr_set = false;
    if (!attr_set) {
        cudaFuncSetAttribute(gemm_mma<__half>, cudaFuncAttributeMaxDynamicSharedMemorySize, SM_TOTAL);
        cudaFuncSetAttribute(gemm_mma<float>, cudaFuncAttributeMaxDynamicSharedMemorySize, SM_TOTAL);
        attr_set = true;
    }

    prep_pre<<<(PREP_TOTAL + 255) / 256, 256>>>(x, w_qkv, w_out, xh, wqh, woh);
    prep_cbias<<<(NMASK * LL + 255) / 256, 256>>>(bias_table, rel_index, mask);

    dim3 g1(N_QKV / GBN, MROWS / GBM);
    gemm_mma<__half><<<g1, 128, SM_TOTAL>>>(xh, wqh, b_qkv, qkvh, MROWS, N_QKV, DMODEL);

    // slot 3 (ncu capture slot): attention
    attn_tc<<<BS * NHEAD, 128>>>();

    dim3 g2(DMODEL / GBN, MROWS / GBM);
    gemm_mma<float><<<g2, 128, SM_TOTAL>>>(ch, woh, b_out, out, MROWS, DMODEL, DMODEL);
}